// round 2
// baseline (speedup 1.0000x reference)
#include <cuda_runtime.h>
#include <math.h>

#define Bv   8
#define Nv   8192
#define Cv   64
#define Pv   2048
#define Kv   16
#define CF   67      // C + 3
#define CP   68      // padded row
#define H1v  64
#define H2v  128
#define EPSv 1e-5f
#define Gv   8       // knn candidate split
#define CHUNK (Nv / Gv)   // 1024

typedef unsigned long long ull;

// scratch (static device globals: allocation-free)
__device__ float  g_fx[(size_t)Bv * Nv * CP];    // packed [feat_t | xyz | 0] per point
__device__ float4 g_xyzq[(size_t)Bv * Nv];       // {x, y, z, |r|^2}
__device__ int    g_knn[(size_t)Bv * Pv * Kv];   // final knn indices
__device__ float  g_pd[(size_t)Bv * Pv * Gv * Kv]; // partial top-16 dists (t-space)
__device__ int    g_pi[(size_t)Bv * Pv * Gv * Kv]; // partial top-16 indices

__device__ __forceinline__ ull fma2(ull a, ull b, ull c) {
    ull d;
    asm("fma.rn.f32x2 %0, %1, %2, %3;" : "=l"(d) : "l"(a), "l"(b), "l"(c));
    return d;
}
__device__ __forceinline__ float sum2(ull a) {
    float lo, hi;
    asm("mov.b64 {%0, %1}, %2;" : "=f"(lo), "=f"(hi) : "l"(a));
    return lo + hi;
}

// ---------------------------------------------------------------------------
// Kernel A: transpose feat (B,C,N) -> fx rows; also build packed xyzq
// ---------------------------------------------------------------------------
__global__ void pack_kernel(const float* __restrict__ xyz,
                            const float* __restrict__ feat) {
    __shared__ float t[64][33];
    int b  = blockIdx.y;
    int n0 = blockIdx.x * 32;
    int tx = threadIdx.x, ty = threadIdx.y;
    #pragma unroll
    for (int c0 = ty; c0 < 64; c0 += 16)
        t[c0][tx] = feat[((size_t)b * Cv + c0) * Nv + n0 + tx];
    if (ty == 0) {
        int n = n0 + tx;
        float x = xyz[((size_t)b * Nv + n) * 3 + 0];
        float y = xyz[((size_t)b * Nv + n) * 3 + 1];
        float z = xyz[((size_t)b * Nv + n) * 3 + 2];
        g_xyzq[(size_t)b * Nv + n] =
            make_float4(x, y, z, fmaf(x, x, fmaf(y, y, z * z)));
    }
    __syncthreads();
    #pragma unroll
    for (int i = ty; i < 32; i += 16) {
        int n = n0 + i;
        float* row = &g_fx[((size_t)b * Nv + n) * CP];
        row[tx]      = t[tx][i];
        row[32 + tx] = t[32 + tx][i];
        if (tx < 3)  row[64 + tx] = xyz[((size_t)b * Nv + n) * 3 + tx];
        if (tx == 3) row[67] = 0.0f;
    }
}

// ---------------------------------------------------------------------------
// Kernel B1: partial KNN — each block scans one 1024-candidate chunk for 128
// queries; keeps per-query top-16 in t-space (t = |r|^2 - 2 q.r).
// ---------------------------------------------------------------------------
__global__ void __launch_bounds__(128) knn_part_kernel() {
    __shared__ float4 sc[CHUNK];
    int b = blockIdx.z, g = blockIdx.y;
    int p = blockIdx.x * 128 + threadIdx.x;
    const float4* xq = g_xyzq + (size_t)b * Nv;

    float4 q = xq[p];
    float m2x = -2.f * q.x, m2y = -2.f * q.y, m2z = -2.f * q.z;

    for (int i = threadIdx.x; i < CHUNK; i += 128)
        sc[i] = xq[g * CHUNK + i];
    __syncthreads();

    float bd[16]; int bi[16];
    #pragma unroll
    for (int i = 0; i < 16; i++) { bd[i] = 3.4e38f; bi[i] = 0; }
    float worst = 3.4e38f; int wslot = 0;

    #pragma unroll 4
    for (int j = 0; j < CHUNK; j++) {
        float4 r = sc[j];
        float t = fmaf(r.x, m2x, fmaf(r.y, m2y, fmaf(r.z, m2z, r.w)));
        if (t < worst) {
            bd[wslot] = t; bi[wslot] = g * CHUNK + j;
            worst = bd[0]; wslot = 0;
            #pragma unroll
            for (int i = 1; i < 16; i++)
                if (bd[i] > worst) { worst = bd[i]; wslot = i; }
        }
    }
    size_t o = (((size_t)b * Pv + p) * Gv + g) * Kv;
    #pragma unroll
    for (int i = 0; i < 16; i++) { g_pd[o + i] = bd[i]; g_pi[o + i] = bi[i]; }
}

// ---------------------------------------------------------------------------
// Kernel B2: merge 8 partial top-16 lists -> final top-16 per query
// ---------------------------------------------------------------------------
__global__ void knn_merge_kernel() {
    int q = blockIdx.x * 256 + threadIdx.x;    // q < B*P
    const float4* pd = (const float4*)(g_pd + (size_t)q * (Gv * Kv));
    const int4*   pi = (const int4*)(g_pi + (size_t)q * (Gv * Kv));

    float bd[16]; int bi[16];
    #pragma unroll
    for (int i = 0; i < 16; i++) { bd[i] = 3.4e38f; bi[i] = 0; }
    float worst = 3.4e38f; int wslot = 0;

    #pragma unroll 4
    for (int v = 0; v < Gv * Kv / 4; v++) {
        float4 d4 = pd[v];
        int4   i4 = pi[v];
        float dv[4] = {d4.x, d4.y, d4.z, d4.w};
        int   iv[4] = {i4.x, i4.y, i4.z, i4.w};
        #pragma unroll
        for (int e = 0; e < 4; e++) {
            if (dv[e] < worst) {
                bd[wslot] = dv[e]; bi[wslot] = iv[e];
                worst = bd[0]; wslot = 0;
                #pragma unroll
                for (int i = 1; i < 16; i++)
                    if (bd[i] > worst) { worst = bd[i]; wslot = i; }
            }
        }
    }
    int* o = g_knn + (size_t)q * Kv;
    #pragma unroll
    for (int i = 0; i < 16; i++) o[i] = bi[i];
}

// ---------------------------------------------------------------------------
// Kernel C: fused gather + MLP(2 layers, folded BN) + max over K.
// One warp per point; packed f32x2 FMA (channel pairs), k-halves of 8 to cap
// register pressure. Smem layout identical to round 1.
// ---------------------------------------------------------------------------
__global__ void __launch_bounds__(256, 2) mlp_kernel(
    const float* __restrict__ W1, const float* __restrict__ b1,
    const float* __restrict__ g1, const float* __restrict__ be1,
    const float* __restrict__ m1, const float* __restrict__ v1,
    const float* __restrict__ W2, const float* __restrict__ b2,
    const float* __restrict__ g2, const float* __restrict__ be2,
    const float* __restrict__ m2, const float* __restrict__ v2,
    float* __restrict__ out) {
    extern __shared__ float sm[];
    float* W1A = sm;
    float* W1D = sm + 4352;
    float* W2S = sm + 8704;
    float* S1  = sm + 17408;
    float* T1  = sm + 17472;
    float* S2  = sm + 17536;
    float* T2  = sm + 17664;
    float* NB  = sm + 17792;
    float* CB  = sm + 26496;
    float* OB  = sm + 27040;

    int tid = threadIdx.x;

    // --- cooperative weight / fold loads ---
    for (int i = tid; i < 64 * CF; i += 256) {
        int o = i / CF, c = i % CF;
        float a = W1[o * 134 + c];
        W1A[o * CP + c] = a;
        W1D[o * CP + c] = W1[o * 134 + CF + c] - a;
    }
    for (int o = tid; o < 64; o += 256) { W1A[o * CP + 67] = 0.f; W1D[o * CP + 67] = 0.f; }
    for (int i = tid; i < 128 * 64; i += 256) {
        int j = i >> 6, o = i & 63;
        W2S[j * CP + o] = W2[i];
    }
    for (int j = tid; j < 128; j += 256) {
        W2S[j * CP + 64] = 0.f; W2S[j * CP + 65] = 0.f;
        W2S[j * CP + 66] = 0.f; W2S[j * CP + 67] = 0.f;
    }
    if (tid < 64) {
        float s = g1[tid] * rsqrtf(v1[tid] + EPSv);
        S1[tid] = s;
        T1[tid] = fmaf(s, b1[tid] - m1[tid], be1[tid]);
    }
    if (tid < 128) {
        float s = g2[tid] * rsqrtf(v2[tid] + EPSv);
        S2[tid] = s;
        T2[tid] = fmaf(s, b2[tid] - m2[tid], be2[tid]);
    }
    __syncthreads();

    int w = tid >> 5, lane = tid & 31;
    int pg = blockIdx.x * 8 + w;
    int b  = pg / Pv, p = pg % Pv;
    const float* fxb = g_fx + (size_t)b * Nv * CP;
    float* NBw = NB + w * (Kv * CP);
    float* CBw = CB + w * CP;

    // --- gather center + neighbors (contiguous float4 rows) ---
    if (lane < 17)
        ((float4*)CBw)[lane] = ((const float4*)(fxb + (size_t)p * CP))[lane];
    const int* kn = g_knn + ((size_t)b * Pv + p) * Kv;
    int myidx = (lane < Kv) ? kn[lane] : 0;
    #pragma unroll
    for (int it = 0; it < 9; it++) {
        int t = lane + it * 32;           // t in [0, 288), valid < 272
        int k = t / 17;
        int kk = (k < 15) ? k : 15;
        int nidx = __shfl_sync(0xffffffffu, myidx, kk);
        if (t < Kv * 17)
            ((float4*)NBw)[t] = ((const float4*)(fxb + (size_t)nidx * CP))[t - kk * 17];
    }
    __syncwarp();

    // --- layer1 base term: center . (W1b - W1a), packed pairs ---
    const float* wd0 = W1D + lane * CP;
    const float* wd1 = W1D + (lane + 32) * CP;
    ull base0 = 0ull, base1 = 0ull;
    #pragma unroll
    for (int ci = 0; ci < 17; ci++) {
        ulonglong2 cv = ((const ulonglong2*)CBw)[ci];
        ulonglong2 d0 = ((const ulonglong2*)wd0)[ci];
        ulonglong2 d1 = ((const ulonglong2*)wd1)[ci];
        base0 = fma2(cv.x, d0.x, base0); base0 = fma2(cv.y, d0.y, base0);
        base1 = fma2(cv.x, d1.x, base1); base1 = fma2(cv.y, d1.y, base1);
    }

    float s1a = S1[lane],      t1a = T1[lane];
    float s1b = S1[lane + 32], t1b = T1[lane + 32];
    const float* wa0 = W1A + lane * CP;
    const float* wa1 = W1A + (lane + 32) * CP;

    // --- layer1 main: two halves of 8 k, packed f32x2 ---
    #pragma unroll
    for (int kh = 0; kh < 2; kh++) {
        ull a0[8], a1[8];
        #pragma unroll
        for (int k = 0; k < 8; k++) { a0[k] = base0; a1[k] = base1; }
        #pragma unroll
        for (int ci = 0; ci < 17; ci++) {
            ulonglong2 w0 = ((const ulonglong2*)wa0)[ci];
            ulonglong2 w1 = ((const ulonglong2*)wa1)[ci];
            #pragma unroll
            for (int k = 0; k < 8; k++) {
                ulonglong2 v = ((const ulonglong2*)(NBw + (kh * 8 + k) * CP))[ci];
                a0[k] = fma2(v.x, w0.x, a0[k]); a0[k] = fma2(v.y, w0.y, a0[k]);
                a1[k] = fma2(v.x, w1.x, a1[k]); a1[k] = fma2(v.y, w1.y, a1[k]);
            }
        }
        __syncwarp();
        #pragma unroll
        for (int k = 0; k < 8; k++) {
            int kk = kh * 8 + k;
            NBw[kk * CP + lane]      = fmaxf(fmaf(s1a, sum2(a0[k]), t1a), 0.f);
            NBw[kk * CP + lane + 32] = fmaxf(fmaf(s1b, sum2(a1[k]), t1b), 0.f);
        }
        __syncwarp();
    }

    // --- layer2 + act2 + max over k, two halves of 8 k ---
    const float* wr0 = W2S + (lane)      * CP;
    const float* wr1 = W2S + (lane + 32) * CP;
    const float* wr2 = W2S + (lane + 64) * CP;
    const float* wr3 = W2S + (lane + 96) * CP;
    float s20 = S2[lane],      t20 = T2[lane];
    float s21 = S2[lane + 32], t21 = T2[lane + 32];
    float s22 = S2[lane + 64], t22 = T2[lane + 64];
    float s23 = S2[lane + 96], t23 = T2[lane + 96];
    float mx0 = 0.f, mx1 = 0.f, mx2 = 0.f, mx3 = 0.f;

    #pragma unroll
    for (int kh = 0; kh < 2; kh++) {
        ull c0[8], c1[8], c2[8], c3[8];
        #pragma unroll
        for (int k = 0; k < 8; k++) { c0[k] = 0; c1[k] = 0; c2[k] = 0; c3[k] = 0; }
        #pragma unroll
        for (int oi = 0; oi < 16; oi++) {
            ulonglong2 u0 = ((const ulonglong2*)wr0)[oi];
            ulonglong2 u1 = ((const ulonglong2*)wr1)[oi];
            ulonglong2 u2 = ((const ulonglong2*)wr2)[oi];
            ulonglong2 u3 = ((const ulonglong2*)wr3)[oi];
            #pragma unroll
            for (int k = 0; k < 8; k++) {
                ulonglong2 h = ((const ulonglong2*)(NBw + (kh * 8 + k) * CP))[oi];
                c0[k] = fma2(h.x, u0.x, c0[k]); c0[k] = fma2(h.y, u0.y, c0[k]);
                c1[k] = fma2(h.x, u1.x, c1[k]); c1[k] = fma2(h.y, u1.y, c1[k]);
                c2[k] = fma2(h.x, u2.x, c2[k]); c2[k] = fma2(h.y, u2.y, c2[k]);
                c3[k] = fma2(h.x, u3.x, c3[k]); c3[k] = fma2(h.y, u3.y, c3[k]);
            }
        }
        #pragma unroll
        for (int k = 0; k < 8; k++) {
            mx0 = fmaxf(mx0, fmaf(s20, sum2(c0[k]), t20));
            mx1 = fmaxf(mx1, fmaf(s21, sum2(c1[k]), t21));
            mx2 = fmaxf(mx2, fmaf(s22, sum2(c2[k]), t22));
            mx3 = fmaxf(mx3, fmaf(s23, sum2(c3[k]), t23));
        }
    }

    OB[(lane)      * 8 + w] = mx0;
    OB[(lane + 32) * 8 + w] = mx1;
    OB[(lane + 64) * 8 + w] = mx2;
    OB[(lane + 96) * 8 + w] = mx3;
    __syncthreads();

    // --- coalesced output: new_feat is (B, 128, P), offset after new_xyz ---
    int pbase = (blockIdx.x * 8) % Pv;
    int bblk  = (blockIdx.x * 8) / Pv;
    float* outF = out + (size_t)Bv * Pv * 3;
    for (int r = tid; r < 128 * 8; r += 256) {
        int j = r >> 3, pi = r & 7;
        outF[((size_t)bblk * H2v + j) * Pv + pbase + pi] = OB[r];
    }
}

// ---------------------------------------------------------------------------
// Kernel D: new_xyz copy + sample_idx
// ---------------------------------------------------------------------------
__global__ void tail_kernel(const float* __restrict__ xyz, float* __restrict__ out) {
    int i = blockIdx.x * 256 + threadIdx.x;
    const int NX = Bv * Pv * 3;
    if (i < NX) {
        int d = i % 3; int rem = i / 3; int p = rem % Pv; int b = rem / Pv;
        out[i] = xyz[((size_t)b * Nv + p) * 3 + d];
    } else if (i < NX + Bv * Pv) {
        int j = i - NX;
        out[(size_t)NX + (size_t)Bv * H2v * Pv + j] = (float)(j % Pv);
    }
}

// ---------------------------------------------------------------------------
extern "C" void kernel_launch(void* const* d_in, const int* in_sizes, int n_in,
                              void* d_out, int out_size) {
    const float* xyz  = (const float*)d_in[0];
    const float* feat = (const float*)d_in[1];
    const float* W1   = (const float*)d_in[2];
    const float* b1   = (const float*)d_in[3];
    const float* g1   = (const float*)d_in[4];
    const float* be1  = (const float*)d_in[5];
    const float* m1   = (const float*)d_in[6];
    const float* v1   = (const float*)d_in[7];
    const float* W2   = (const float*)d_in[8];
    const float* b2   = (const float*)d_in[9];
    const float* g2   = (const float*)d_in[10];
    const float* be2  = (const float*)d_in[11];
    const float* m2   = (const float*)d_in[12];
    const float* v2   = (const float*)d_in[13];
    float* out = (float*)d_out;

    const int SMEM_BYTES = 28064 * 4;
    cudaFuncSetAttribute(mlp_kernel, cudaFuncAttributeMaxDynamicSharedMemorySize,
                         SMEM_BYTES);

    pack_kernel<<<dim3(Nv / 32, Bv), dim3(32, 16)>>>(xyz, feat);
    knn_part_kernel<<<dim3(Pv / 128, Gv, Bv), 128>>>();
    knn_merge_kernel<<<(Bv * Pv) / 256, 256>>>();
    mlp_kernel<<<Bv * Pv / 8, 256, SMEM_BYTES>>>(W1, b1, g1, be1, m1, v1,
                                                 W2, b2, g2, be2, m2, v2, out);
    tail_kernel<<<256, 256>>>(xyz, out);
}